// round 1
// baseline (speedup 1.0000x reference)
#include <cuda_runtime.h>
#include <math.h>

#define NN 10000
#define NE 320000
#define FIN 512
#define HIDC 256
#define ZC 64
#define NH 8
#define ND0 32
#define ND1 8
#define NEG_SLOPE 0.2f

// ---------------- scratch (static device memory; no allocations) ----------------
__device__ float g_lin0[NN * HIDC];   // layer0 linear out  (h = x@W0)
__device__ float g_gat0[NN * HIDC];   // layer0 GAT out (input to layers 1/2)
__device__ float g_lin1[NN * ZC];
__device__ float g_lin2[NN * ZC];
__device__ float g_mean[NN * ZC];
__device__ float g_lstd[NN * ZC];
__device__ float g_el[NN * NH];
__device__ float g_er[NN * NH];
__device__ float g_m[NN * NH];
__device__ float g_s[NN * NH];
__device__ float g_e[NE * NH];        // per-edge e / ex values, SORTED edge order
__device__ int   g_deg[NN];
__device__ int   g_off[NN + 1];
__device__ int   g_cur[NN];
__device__ int   g_ssrc[NE];          // src per sorted edge
__device__ int   g_sdst[NE];          // dst per sorted edge

// ---------------- counting sort of edges by dst ----------------
__global__ void k_zero_deg() {
    int i = blockIdx.x * blockDim.x + threadIdx.x;
    if (i < NN) g_deg[i] = 0;
}

__global__ void k_hist(const int* __restrict__ dst) {
    int i = blockIdx.x * blockDim.x + threadIdx.x;
    if (i < NE) atomicAdd(&g_deg[dst[i]], 1);
}

// single-block exclusive scan over NN degrees
__global__ void k_scan() {
    const int CH = 10;  // 1024*10 >= NN
    __shared__ int sh[1024];
    int t = threadIdx.x;
    int base = t * CH;
    int vals[CH];
    int loc = 0;
#pragma unroll
    for (int i = 0; i < CH; i++) {
        int idx = base + i;
        vals[i] = (idx < NN) ? g_deg[idx] : 0;
        loc += vals[i];
    }
    sh[t] = loc;
    __syncthreads();
    for (int off = 1; off < 1024; off <<= 1) {
        int v = (t >= off) ? sh[t - off] : 0;
        __syncthreads();
        sh[t] += v;
        __syncthreads();
    }
    int run = sh[t] - loc;  // exclusive prefix of this thread's chunk
#pragma unroll
    for (int i = 0; i < CH; i++) {
        int idx = base + i;
        if (idx < NN) {
            g_off[idx] = run;
            g_cur[idx] = run;
            run += vals[i];
        }
    }
    if (t == 0) g_off[NN] = NE;
}

__global__ void k_scatter(const int* __restrict__ src, const int* __restrict__ dst) {
    int e = blockIdx.x * blockDim.x + threadIdx.x;
    if (e < NE) {
        int d = dst[e];
        int pos = atomicAdd(&g_cur[d], 1);
        g_ssrc[pos] = src[e];
        g_sdst[pos] = d;
    }
}

// ---------------- fp32 tiled GEMM: C[M,Nn] = A[M,K] @ B[K,Nn] ----------------
// Requires K % 32 == 0, Nn % 64 == 0. M guarded.
__global__ __launch_bounds__(256) void k_sgemm(const float* __restrict__ A,
                                               const float* __restrict__ B,
                                               float* __restrict__ C,
                                               int M, int K, int Nn) {
    __shared__ float As[64 * 32];   // [row][k]
    __shared__ float Bs[32 * 64];   // [k][col]
    int tid = threadIdx.x;
    int tx = tid & 15, ty = tid >> 4;
    int rowBase = blockIdx.y * 64;
    int colBase = blockIdx.x * 64;
    float acc[4][4] = {};

    for (int kb = 0; kb < K; kb += 32) {
        {
            int r = tid >> 3;
            int c = (tid & 7) << 2;
#pragma unroll
            for (int p = 0; p < 2; p++) {
                int rr = r + p * 32;
                int grow = rowBase + rr;
                float4 v = make_float4(0.f, 0.f, 0.f, 0.f);
                if (grow < M) v = *(const float4*)(A + (size_t)grow * K + kb + c);
                *(float4*)(As + rr * 32 + c) = v;
            }
            int r2 = tid >> 4;
            int c2 = (tid & 15) << 2;
#pragma unroll
            for (int p = 0; p < 2; p++) {
                int rr = r2 + p * 16;
                float4 v = *(const float4*)(B + (size_t)(kb + rr) * Nn + colBase + c2);
                *(float4*)(Bs + rr * 64 + c2) = v;
            }
        }
        __syncthreads();
#pragma unroll
        for (int kk = 0; kk < 32; kk++) {
            float4 b0 = *(const float4*)(Bs + kk * 64 + tx * 4);
            float a0 = As[(ty * 4 + 0) * 32 + kk];
            float a1 = As[(ty * 4 + 1) * 32 + kk];
            float a2 = As[(ty * 4 + 2) * 32 + kk];
            float a3 = As[(ty * 4 + 3) * 32 + kk];
            acc[0][0] += a0 * b0.x; acc[0][1] += a0 * b0.y; acc[0][2] += a0 * b0.z; acc[0][3] += a0 * b0.w;
            acc[1][0] += a1 * b0.x; acc[1][1] += a1 * b0.y; acc[1][2] += a1 * b0.z; acc[1][3] += a1 * b0.w;
            acc[2][0] += a2 * b0.x; acc[2][1] += a2 * b0.y; acc[2][2] += a2 * b0.z; acc[2][3] += a2 * b0.w;
            acc[3][0] += a3 * b0.x; acc[3][1] += a3 * b0.y; acc[3][2] += a3 * b0.z; acc[3][3] += a3 * b0.w;
        }
        __syncthreads();
    }
#pragma unroll
    for (int i = 0; i < 4; i++) {
        int grow = rowBase + ty * 4 + i;
        if (grow < M) {
            *(float4*)(C + (size_t)grow * Nn + colBase + tx * 4) =
                make_float4(acc[i][0], acc[i][1], acc[i][2], acc[i][3]);
        }
    }
}

// ---------------- el/er: per (node, head) dot over D ----------------
template <int D>
__global__ void k_elr(const float* __restrict__ lin,
                      const float* __restrict__ al,
                      const float* __restrict__ ar) {
    int i = blockIdx.x * blockDim.x + threadIdx.x;
    if (i >= NN * NH) return;
    int n = i / NH, h = i % NH;
    float el = 0.f, er = 0.f;
#pragma unroll
    for (int d = 0; d < D; d++) {
        float v = lin[n * (NH * D) + h * D + d];
        el += v * al[h * D + d];
        er += v * ar[h * D + d];
    }
    g_el[i] = el;
    g_er[i] = er;
}

__global__ void k_init_ms() {
    int i = blockIdx.x * blockDim.x + threadIdx.x;
    if (i < NN * NH) {
        g_m[i] = -INFINITY;
        g_s[i] = 0.f;
    }
}

__device__ __forceinline__ void atomicMaxFloat(float* addr, float val) {
    if (val >= 0.f)
        atomicMax((int*)addr, __float_as_int(val));
    else
        atomicMin((unsigned int*)addr, (unsigned int)__float_as_int(val));
}

// e = leaky_relu(el[src]+er[dst]); store (sorted order); atomicMax m[dst,h]
__global__ void k_edge1() {
    int idx = blockIdx.x * blockDim.x + threadIdx.x;
    if (idx >= NE * NH) return;
    int j = idx >> 3;     // sorted edge index
    int h = idx & 7;
    int s = g_ssrc[j];
    int d = g_sdst[j];
    float v = g_el[s * NH + h] + g_er[d * NH + h];
    v = (v > 0.f) ? v : NEG_SLOPE * v;
    g_e[idx] = v;
    atomicMaxFloat(&g_m[d * NH + h], v);
}

// ex = exp(e - m[dst,h]); store; atomicAdd s[dst,h]
__global__ void k_edge2() {
    int idx = blockIdx.x * blockDim.x + threadIdx.x;
    if (idx >= NE * NH) return;
    int j = idx >> 3;
    int h = idx & 7;
    int d = g_sdst[j];
    float ex = expf(g_e[idx] - g_m[d * NH + h]);
    g_e[idx] = ex;
    atomicAdd(&g_s[d * NH + h], ex);
}

// ---------------- CSR aggregation: out[n,c] = act(sum_e h[src,c]*ex[e,h]/s + b) ----------------
template <int D, bool RELU>
__global__ void k_agg(const float* __restrict__ lin,
                      const float* __restrict__ bias,
                      float* __restrict__ out) {
    const int C = NH * D;
    int n = blockIdx.x;
    int tid = threadIdx.x;     // 0..C-1
    int h = tid / D;
    int beg = g_off[n], end = g_off[n + 1];
    float acc = 0.f;
    __shared__ int s_src[32];
    __shared__ float s_ex[32 * NH];
    for (int base = beg; base < end; base += 32) {
        int cnt = min(32, end - base);
        __syncthreads();
        if (tid < cnt) s_src[tid] = g_ssrc[base + tid];
        for (int i = tid; i < cnt * NH; i += C) s_ex[i] = g_e[base * NH + i];
        __syncthreads();
        for (int jj = 0; jj < cnt; jj++) {
            acc += lin[(size_t)s_src[jj] * C + tid] * s_ex[jj * NH + h];
        }
    }
    float v = (end > beg) ? (acc / g_s[n * NH + h]) : 0.f;
    v += bias[tid];
    if (RELU) v = fmaxf(v, 0.f);
    out[(size_t)n * C + tid] = v;
}

// ---------------- z = mean + noise * exp(log_std) ----------------
__global__ void k_z(const float* __restrict__ noise, float* __restrict__ zout) {
    int i = blockIdx.x * blockDim.x + threadIdx.x;
    if (i < NN * ZC) zout[i] = g_mean[i] + noise[i] * expf(g_lstd[i]);
}

// ---------------- adj = sigmoid(z @ z^T), 128x128 tiles, 8x8 per thread ----------------
#define ADJ_LDT 132
#define ADJ_SMEM (2 * 64 * ADJ_LDT * 4)
__global__ __launch_bounds__(256) void k_adj(const float* __restrict__ z,
                                             float* __restrict__ adj) {
    extern __shared__ float sm[];
    float* Azt = sm;                   // [k][row_local]  64 x ADJ_LDT
    float* Bzt = sm + 64 * ADJ_LDT;    // [k][col_local]
    int tid = threadIdx.x;
    int tx = tid & 15, ty = tid >> 4;
    int row0 = blockIdx.y * 128;
    int col0 = blockIdx.x * 128;

#pragma unroll
    for (int p = 0; p < 8; p++) {
        int nl = p * 16 + (tid >> 4);
        int k4 = (tid & 15) << 2;
        int ra = row0 + nl;
        float4 va = (ra < NN) ? *(const float4*)(z + (size_t)ra * ZC + k4)
                              : make_float4(0.f, 0.f, 0.f, 0.f);
        Azt[(k4 + 0) * ADJ_LDT + nl] = va.x;
        Azt[(k4 + 1) * ADJ_LDT + nl] = va.y;
        Azt[(k4 + 2) * ADJ_LDT + nl] = va.z;
        Azt[(k4 + 3) * ADJ_LDT + nl] = va.w;
        int rb = col0 + nl;
        float4 vb = (rb < NN) ? *(const float4*)(z + (size_t)rb * ZC + k4)
                              : make_float4(0.f, 0.f, 0.f, 0.f);
        Bzt[(k4 + 0) * ADJ_LDT + nl] = vb.x;
        Bzt[(k4 + 1) * ADJ_LDT + nl] = vb.y;
        Bzt[(k4 + 2) * ADJ_LDT + nl] = vb.z;
        Bzt[(k4 + 3) * ADJ_LDT + nl] = vb.w;
    }
    __syncthreads();

    float acc[8][8] = {};
#pragma unroll
    for (int k = 0; k < 64; k++) {
        float4 a0 = *(const float4*)(Azt + k * ADJ_LDT + ty * 8);
        float4 a1 = *(const float4*)(Azt + k * ADJ_LDT + ty * 8 + 4);
        float4 b0 = *(const float4*)(Bzt + k * ADJ_LDT + tx * 8);
        float4 b1 = *(const float4*)(Bzt + k * ADJ_LDT + tx * 8 + 4);
        float a[8] = {a0.x, a0.y, a0.z, a0.w, a1.x, a1.y, a1.z, a1.w};
        float b[8] = {b0.x, b0.y, b0.z, b0.w, b1.x, b1.y, b1.z, b1.w};
#pragma unroll
        for (int i = 0; i < 8; i++)
#pragma unroll
            for (int jj = 0; jj < 8; jj++) acc[i][jj] += a[i] * b[jj];
    }

#pragma unroll
    for (int i = 0; i < 8; i++) {
        int r = row0 + ty * 8 + i;
        if (r >= NN) continue;
        float* outrow = adj + (size_t)r * NN;
        int c = col0 + tx * 8;
#pragma unroll
        for (int jj = 0; jj < 8; jj++) acc[i][jj] = 1.f / (1.f + __expf(-acc[i][jj]));
        if (c + 7 < NN) {
            *(float4*)(outrow + c) = make_float4(acc[i][0], acc[i][1], acc[i][2], acc[i][3]);
            *(float4*)(outrow + c + 4) = make_float4(acc[i][4], acc[i][5], acc[i][6], acc[i][7]);
        } else {
#pragma unroll
            for (int jj = 0; jj < 8; jj++)
                if (c + jj < NN) outrow[c + jj] = acc[i][jj];
        }
    }
}

// ---------------- launcher ----------------
extern "C" void kernel_launch(void* const* d_in, const int* in_sizes, int n_in,
                              void* d_out, int out_size) {
    const float* features = (const float*)d_in[0];
    const int*   src      = (const int*)d_in[1];
    const int*   dst      = (const int*)d_in[2];
    const float* noise    = (const float*)d_in[3];
    const float* W0  = (const float*)d_in[4];
    const float* al0 = (const float*)d_in[5];
    const float* ar0 = (const float*)d_in[6];
    const float* b0  = (const float*)d_in[7];
    const float* W1  = (const float*)d_in[8];
    const float* al1 = (const float*)d_in[9];
    const float* ar1 = (const float*)d_in[10];
    const float* b1  = (const float*)d_in[11];
    const float* W2  = (const float*)d_in[12];
    const float* al2 = (const float*)d_in[13];
    const float* ar2 = (const float*)d_in[14];
    const float* b2  = (const float*)d_in[15];

    float* out = (float*)d_out;
    float* z_out = out;
    float* adj_out = out + (size_t)NN * ZC;

    void* p;
    cudaGetSymbolAddress(&p, g_lin0); float* lin0 = (float*)p;
    cudaGetSymbolAddress(&p, g_gat0); float* gat0 = (float*)p;
    cudaGetSymbolAddress(&p, g_lin1); float* lin1 = (float*)p;
    cudaGetSymbolAddress(&p, g_lin2); float* lin2 = (float*)p;
    cudaGetSymbolAddress(&p, g_mean); float* meanp = (float*)p;
    cudaGetSymbolAddress(&p, g_lstd); float* lstdp = (float*)p;

    // edge sort by dst (shared by all 3 GAT layers)
    k_zero_deg<<<(NN + 255) / 256, 256>>>();
    k_hist<<<(NE + 255) / 256, 256>>>(dst);
    k_scan<<<1, 1024>>>();
    k_scatter<<<(NE + 255) / 256, 256>>>(src, dst);

    const int egrid = (NE * NH + 255) / 256;
    const int ngrid = (NN * NH + 255) / 256;

    // ---- layer 0: 512 -> 256, relu ----
    k_sgemm<<<dim3(HIDC / 64, (NN + 63) / 64), 256>>>(features, W0, lin0, NN, FIN, HIDC);
    k_elr<ND0><<<ngrid, 256>>>(lin0, al0, ar0);
    k_init_ms<<<ngrid, 256>>>();
    k_edge1<<<egrid, 256>>>();
    k_edge2<<<egrid, 256>>>();
    k_agg<ND0, true><<<NN, NH * ND0>>>(lin0, b0, gat0);

    // ---- layer 1 (mean): 256 -> 64 ----
    k_sgemm<<<dim3(ZC / 64, (NN + 63) / 64), 256>>>(gat0, W1, lin1, NN, HIDC, ZC);
    k_elr<ND1><<<ngrid, 256>>>(lin1, al1, ar1);
    k_init_ms<<<ngrid, 256>>>();
    k_edge1<<<egrid, 256>>>();
    k_edge2<<<egrid, 256>>>();
    k_agg<ND1, false><<<NN, NH * ND1>>>(lin1, b1, meanp);

    // ---- layer 2 (log_std): 256 -> 64 ----
    k_sgemm<<<dim3(ZC / 64, (NN + 63) / 64), 256>>>(gat0, W2, lin2, NN, HIDC, ZC);
    k_elr<ND1><<<ngrid, 256>>>(lin2, al2, ar2);
    k_init_ms<<<ngrid, 256>>>();
    k_edge1<<<egrid, 256>>>();
    k_edge2<<<egrid, 256>>>();
    k_agg<ND1, false><<<NN, NH * ND1>>>(lin2, b2, lstdp);

    // ---- z = mean + noise * exp(log_std) ----
    k_z<<<(NN * ZC + 255) / 256, 256>>>(noise, z_out);

    // ---- adj = sigmoid(z @ z^T) ----
    cudaFuncSetAttribute(k_adj, cudaFuncAttributeMaxDynamicSharedMemorySize, ADJ_SMEM);
    k_adj<<<dim3((NN + 127) / 128, (NN + 127) / 128), 256, ADJ_SMEM>>>(z_out, adj_out);
}